// round 5
// baseline (speedup 1.0000x reference)
#include <cuda_runtime.h>
#include <math.h>

#define LSEQ 4096      // L = 16*16*16
#define NSq  8         // 4 parts * B=2 sequences
#define DI   128       // d_inner
#define DST  16        // d_state
#define NCHK 128       // scan chunks
#define CLEN 32        // chunk length
#define NCHAN (NSq*DI*DST)   // 16384 channels

// ---------------- static device scratch ----------------
__device__ float g_parts[NSq*LSEQ*64];
__device__ float g_uraw [NSq*LSEQ*DI];   // pre-conv u; reused as gated-y by K4
__device__ float g_zbuf [NSq*LSEQ*DI];
__device__ float g_ubuf [NSq*LSEQ*DI];
__device__ float g_dt   [NSq*LSEQ*DI];
__device__ float g_Bm   [NSq*LSEQ*DST];
__device__ float g_Cm   [NSq*LSEQ*DST];
__device__ float g_Ap   [NCHK*NCHAN];
__device__ float g_Bp   [NCHK*NCHAN];
__device__ float g_Hc   [NCHK*NCHAN];
__device__ float g_xm   [2*LSEQ*256];
__device__ int   g_fast;

// ---------------- K0: detect A[d][k] == -(k+1) ----------------
__global__ void k0_check(const float* __restrict__ A_log) {
    __shared__ int ok;
    if (threadIdx.x == 0) ok = 1;
    __syncthreads();
    for (int i = threadIdx.x; i < DI*DST; i += blockDim.x) {
        int k = i & 15;
        float a = __expf(A_log[i]);
        if (fabsf(a - (float)(k + 1)) > 1e-3f * (float)(k + 1)) atomicAnd(&ok, 0);
    }
    __syncthreads();
    if (threadIdx.x == 0) g_fast = ok;
}

// ---------------- K1: LayerNorm + parts + in_proj ----------------
// grid (L/16, B, 2 e-halves), 256 threads, ~52KB smem -> 4 blocks/SM
__global__ void __launch_bounds__(256)
k1_ln_inproj(const float* __restrict__ x, const float* __restrict__ lng,
             const float* __restrict__ lnb, const float* __restrict__ W) {
    extern __shared__ float sm[];
    float* xs  = sm;             // 16 x 257
    float* ws  = xs + 16*257;    // 64 x 132  W^T chunk [d][e_local]
    float* gs  = ws + 64*132;    // 256
    float* bs  = gs + 256;       // 256
    float* mus = bs + 256;       // 16
    float* rss = mus + 16;       // 16

    const int tid = threadIdx.x;
    const int b   = blockIdx.y;
    const int z   = blockIdx.z;
    const int l0  = blockIdx.x * 16;

    #pragma unroll 4
    for (int i = 0; i < 32; i++) {           // W^T chunk
        int idx = i*256 + tid;
        int el = idx >> 6, d = idx & 63;
        ws[d*132 + el] = W[(z*128 + el)*64 + d];
    }
    gs[tid] = lng[tid]; bs[tid] = lnb[tid];

    #pragma unroll 4
    for (int i = 0; i < 16; i++) {           // x tile -> xs[l][c]
        int idx = i*256 + tid;
        int c = idx >> 4, ll = idx & 15;
        xs[ll*257 + c] = x[(b*256 + c)*LSEQ + l0 + ll];
    }
    __syncthreads();

    const int w = tid >> 5, lane = tid & 31;
    for (int i = 0; i < 2; i++) {            // LN stats: 8 warps x 2 rows
        int ll = w*2 + i;
        float s = 0.f, s2 = 0.f;
        #pragma unroll
        for (int j = 0; j < 8; j++) {
            float v = xs[ll*257 + lane + j*32];
            s += v; s2 += v*v;
        }
        #pragma unroll
        for (int o = 16; o > 0; o >>= 1) {
            s  += __shfl_xor_sync(0xffffffffu, s,  o);
            s2 += __shfl_xor_sync(0xffffffffu, s2, o);
        }
        if (lane == 0) {
            float mu = s * (1.f/256.f);
            mus[ll] = mu;
            rss[ll] = rsqrtf(s2 * (1.f/256.f) - mu*mu + 1e-5f);
        }
    }
    __syncthreads();

    #pragma unroll
    for (int ll = 0; ll < 16; ll++) {        // normalize (+ parts once)
        int c = tid;
        float v = (xs[ll*257 + c] - mus[ll]) * rss[ll] * gs[c] + bs[c];
        xs[ll*257 + c] = v;
        if (z == 0) {
            int p = c >> 6, cq = c & 63;
            g_parts[((p*2 + b)*LSEQ + l0 + ll)*64 + cq] = v;
        }
    }
    __syncthreads();

    // in_proj: thread = (te 32, tl 8); e_local = te*4, l = tl*2 + j
    const int te = tid >> 3, tl = tid & 7;
    const int e0 = te*4;
    for (int p = 0; p < 4; p++) {
        float a0[2], a1[2], a2[2], a3[2];
        #pragma unroll
        for (int j = 0; j < 2; j++) { a0[j]=0.f; a1[j]=0.f; a2[j]=0.f; a3[j]=0.f; }
        #pragma unroll 4
        for (int d = 0; d < 64; d++) {
            float4 wv = *(const float4*)&ws[d*132 + e0];
            #pragma unroll
            for (int j = 0; j < 2; j++) {
                float xv = xs[(tl*2 + j)*257 + p*64 + d];
                a0[j] += wv.x * xv;
                a1[j] += wv.y * xv;
                a2[j] += wv.z * xv;
                a3[j] += wv.w * xv;
            }
        }
        const int s = p*2 + b;
        #pragma unroll
        for (int j = 0; j < 2; j++) {
            int l = l0 + tl*2 + j;
            float4 val = make_float4(a0[j], a1[j], a2[j], a3[j]);
            if (z == 0) *(float4*)&g_uraw[(s*LSEQ + l)*128 + e0] = val;
            else        *(float4*)&g_zbuf[(s*LSEQ + l)*128 + e0] = val;
        }
    }
}

// ---------------- K2: conv + silu + x_proj + dt_proj + softplus ----------------
// grid (L/16, NSq), 256 threads, ~46KB -> 4 blocks/SM
__global__ void __launch_bounds__(256)
k2_conv(const float* __restrict__ cw, const float* __restrict__ cb,
        const float* __restrict__ xw, const float* __restrict__ dtw,
        const float* __restrict__ dtb) {
    extern __shared__ float sm[];
    float* ur   = sm;              // 19 x 130 (3 halo + 16)
    float* us   = ur + 19*130;     // 16 x 130
    float* xws  = us + 16*130;     // 36 x 130
    float* dbc  = xws + 36*130;    // 16 x 40
    float* cws  = dbc + 16*40;     // 128 x 5
    float* dtws = cws + 128*5;     // 128 x 5
    float* cbs  = dtws + 128*5;    // 128
    float* dtbs = cbs + 128;       // 128

    const int tid = threadIdx.x;
    const int s   = blockIdx.y;
    const int l0  = blockIdx.x * 16;

    for (int i = tid; i < 128*4; i += 256) {
        int ch = i >> 2, j = i & 3;
        cws[ch*5 + j]  = cw[i];
        dtws[ch*5 + j] = dtw[i];
    }
    if (tid < 128) { cbs[tid] = cb[tid]; dtbs[tid] = dtb[tid]; }
    for (int i = tid; i < 36*128; i += 256) {
        int e = i >> 7, ch = i & 127;
        xws[e*130 + ch] = xw[i];
    }
    for (int i = tid; i < 19*128; i += 256) {
        int r = i >> 7, ch = i & 127;
        int l = l0 - 3 + r;
        ur[r*130 + ch] = (l >= 0) ? g_uraw[(s*LSEQ + l)*128 + ch] : 0.f;
    }
    __syncthreads();

    for (int i = tid; i < 16*128; i += 256) {     // conv + silu
        int ll = i >> 7, ch = i & 127;
        float a = cbs[ch];
        #pragma unroll
        for (int j = 0; j < 4; j++) a += cws[ch*5 + j] * ur[(ll + j)*130 + ch];
        float v = a / (1.f + __expf(-a));
        us[ll*130 + ch] = v;
        g_ubuf[(s*LSEQ + l0 + ll)*128 + ch] = v;
    }
    __syncthreads();

    for (int i = tid; i < 16*36; i += 256) {      // x_proj
        int ll = i / 36, e = i % 36;
        float a = 0.f;
        #pragma unroll 8
        for (int ch = 0; ch < 128; ch++) a += us[ll*130 + ch] * xws[e*130 + ch];
        dbc[ll*40 + e] = a;
    }
    __syncthreads();

    for (int i = tid; i < 16*16; i += 256) {      // write B, C
        int ll = i >> 4, k = i & 15;
        g_Bm[(s*LSEQ + l0 + ll)*16 + k] = dbc[ll*40 + 4 + k];
        g_Cm[(s*LSEQ + l0 + ll)*16 + k] = dbc[ll*40 + 20 + k];
    }
    for (int i = tid; i < 16*128; i += 256) {     // dt_proj + softplus
        int ll = i >> 7, d = i & 127;
        float a = dtbs[d];
        #pragma unroll
        for (int r = 0; r < 4; r++) a += dbc[ll*40 + r] * dtws[d*5 + r];
        float sp = (a > 20.f) ? a : log1pf(__expf(a));
        g_dt[(s*LSEQ + l0 + ll)*128 + d] = sp;
    }
}

// 8-power tree: q[j] = p^(j+1), 7 FMUL
__device__ __forceinline__ void pow_tree8(float p, float* q) {
    float p2 = p*p, p4 = p2*p2;
    q[0]=p;     q[1]=p2;    q[2]=p2*p;  q[3]=p4;
    q[4]=p4*p;  q[5]=p4*p2; q[6]=p4*q[2]; q[7]=p4*p4;
}

// ---------------- K3: scan pass 1, 8 states/thread ----------------
// grid (NCHK, NSq), 256 threads: d = tid&127, kh = tid>>7
__global__ void __launch_bounds__(256)
k3_scan1(const float* __restrict__ A_log) {
    __shared__ float Bsh[CLEN*20];
    const int tid = threadIdx.x;
    const int d   = tid & 127;
    const int kh  = tid >> 7;       // warp-uniform
    const int s   = blockIdx.y;
    const int c   = blockIdx.x;
    const int l0  = c * CLEN;

    for (int i = tid; i < CLEN*16; i += 256) {
        int l = i >> 4, k = i & 15;
        Bsh[l*20 + k] = g_Bm[(s*LSEQ + l0 + l)*16 + k];
    }
    const int fast = g_fast;
    float Areg[8];
    if (!fast) {
        #pragma unroll
        for (int k = 0; k < 8; k++) Areg[k] = -__expf(A_log[d*16 + kh*8 + k]);
    }
    __syncthreads();

    float h[8];
    #pragma unroll
    for (int k = 0; k < 8; k++) h[k] = 0.f;
    const float* pdt = g_dt   + (s*LSEQ + l0)*128 + d;
    const float* pu  = g_ubuf + (s*LSEQ + l0)*128 + d;
    const int ch = (s*128 + d)*16 + kh*8;

    if (fast) {
        float P = 1.f;
        #pragma unroll 4
        for (int l = 0; l < CLEN; l++) {
            float dt = pdt[l*128];
            float du = dt * pu[l*128];
            float p  = __expf(-dt);
            P *= p;
            float q[8]; pow_tree8(p, q);
            if (kh) {                         // warp-uniform branch
                float p8 = q[7];
                #pragma unroll
                for (int j = 0; j < 8; j++) q[j] *= p8;
            }
            float4 b0 = *(const float4*)&Bsh[l*20 + kh*8];
            float4 b1 = *(const float4*)&Bsh[l*20 + kh*8 + 4];
            h[0] = q[0]*h[0] + du*b0.x;  h[1] = q[1]*h[1] + du*b0.y;
            h[2] = q[2]*h[2] + du*b0.z;  h[3] = q[3]*h[3] + du*b0.w;
            h[4] = q[4]*h[4] + du*b1.x;  h[5] = q[5]*h[5] + du*b1.y;
            h[6] = q[6]*h[6] + du*b1.z;  h[7] = q[7]*h[7] + du*b1.w;
        }
        float P2 = P*P, P4 = P2*P2, P8 = P4*P4;
        float Q = kh ? P8*P : P;
        #pragma unroll
        for (int k = 0; k < 8; k++) {
            g_Ap[c*NCHAN + ch + k] = Q;
            g_Bp[c*NCHAN + ch + k] = h[k];
            Q *= P;
        }
    } else {
        float ap[8];
        #pragma unroll
        for (int k = 0; k < 8; k++) ap[k] = 1.f;
        #pragma unroll 2
        for (int l = 0; l < CLEN; l++) {
            float dt = pdt[l*128];
            float du = dt * pu[l*128];
            const float* pB = &Bsh[l*20 + kh*8];
            #pragma unroll
            for (int k = 0; k < 8; k++) {
                float a = __expf(dt * Areg[k]);
                h[k]  = a*h[k] + du*pB[k];
                ap[k] *= a;
            }
        }
        #pragma unroll
        for (int k = 0; k < 8; k++) {
            g_Ap[c*NCHAN + ch + k] = ap[k];
            g_Bp[c*NCHAN + ch + k] = h[k];
        }
    }
}

// ---------------- K3b: inter-chunk carry scan ----------------
__global__ void __launch_bounds__(256)
k3b_carry() {
    int ch = blockIdx.x*256 + threadIdx.x;
    float h = 0.f;
    #pragma unroll 4
    for (int c = 0; c < NCHK; c++) {
        g_Hc[c*NCHAN + ch] = h;
        h = g_Ap[c*NCHAN + ch]*h + g_Bp[c*NCHAN + ch];
    }
}

// ---------------- K4: scan pass 2 + gate -> y in g_uraw ----------------
// grid (NCHK, NSq), 256 threads. warp w: d = w*16 + (lane&15), kh = lane>>4
__global__ void __launch_bounds__(256)
k4_scan2(const float* __restrict__ A_log, const float* __restrict__ Dp) {
    __shared__ float Bsh[CLEN*20];
    __shared__ float Csh[CLEN*20];
    const int tid  = threadIdx.x;
    const int w    = tid >> 5, lane = tid & 31;
    const int d    = w*16 + (lane & 15);
    const int kh   = lane >> 4;       // half-warp uniform
    const int s    = blockIdx.y;
    const int c    = blockIdx.x;
    const int l0   = c * CLEN;

    for (int i = tid; i < CLEN*16; i += 256) {
        int l = i >> 4, k = i & 15;
        Bsh[l*20 + k] = g_Bm[(s*LSEQ + l0 + l)*16 + k];
        Csh[l*20 + k] = g_Cm[(s*LSEQ + l0 + l)*16 + k];
    }
    const int fast = g_fast;
    float Areg[8];
    if (!fast) {
        #pragma unroll
        for (int k = 0; k < 8; k++) Areg[k] = -__expf(A_log[d*16 + kh*8 + k]);
    }
    float h[8];
    {
        const int ch = (s*128 + d)*16 + kh*8;
        #pragma unroll
        for (int k = 0; k < 8; k++) h[k] = g_Hc[c*NCHAN + ch + k];
    }
    const float Dd = Dp[d];
    __syncthreads();

    const float* pdt = g_dt   + (s*LSEQ + l0)*128 + d;
    const float* pu  = g_ubuf + (s*LSEQ + l0)*128 + d;
    const float* pz  = g_zbuf + (s*LSEQ + l0)*128 + d;
    float*       py  = g_uraw + (s*LSEQ + l0)*128 + d;

    if (fast) {
        #pragma unroll 2
        for (int l = 0; l < CLEN; l++) {
            float dt = pdt[l*128];
            float uu = pu[l*128];
            float zv = pz[l*128];
            float du = dt * uu;
            float p  = __expf(-dt);
            float q[8]; pow_tree8(p, q);
            float p8m = kh ? q[7] : 1.f;
            #pragma unroll
            for (int j = 0; j < 8; j++) q[j] *= p8m;
            float4 b0 = *(const float4*)&Bsh[l*20 + kh*8];
            float4 b1 = *(const float4*)&Bsh[l*20 + kh*8 + 4];
            float4 c0 = *(const float4*)&Csh[l*20 + kh*8];
            float4 c1 = *(const float4*)&Csh[l*20 + kh*8 + 4];
            float y = kh ? 0.f : Dd * uu;
            h[0] = q[0]*h[0] + du*b0.x;  y += h[0]*c0.x;
            h[1] = q[1]*h[1] + du*b0.y;  y += h[1]*c0.y;
            h[2] = q[2]*h[2] + du*b0.z;  y += h[2]*c0.z;
            h[3] = q[3]*h[3] + du*b0.w;  y += h[3]*c0.w;
            h[4] = q[4]*h[4] + du*b1.x;  y += h[4]*c1.x;
            h[5] = q[5]*h[5] + du*b1.y;  y += h[5]*c1.y;
            h[6] = q[6]*h[6] + du*b1.z;  y += h[6]*c1.z;
            h[7] = q[7]*h[7] + du*b1.w;  y += h[7]*c1.w;
            y += __shfl_xor_sync(0xffffffffu, y, 16);
            float sg = 1.f / (1.f + __expf(-zv));
            if (kh == 0) py[l*128] = y * zv * sg;
        }
    } else {
        #pragma unroll 2
        for (int l = 0; l < CLEN; l++) {
            float dt = pdt[l*128];
            float uu = pu[l*128];
            float zv = pz[l*128];
            float du = dt * uu;
            const float* pB = &Bsh[l*20 + kh*8];
            const float* pC = &Csh[l*20 + kh*8];
            float y = kh ? 0.f : Dd * uu;
            #pragma unroll
            for (int k = 0; k < 8; k++) {
                float a = __expf(dt * Areg[k]);
                h[k] = a*h[k] + du*pB[k];
                y   += h[k]*pC[k];
            }
            y += __shfl_xor_sync(0xffffffffu, y, 16);
            float sg = 1.f / (1.f + __expf(-zv));
            if (kh == 0) py[l*128] = y * zv * sg;
        }
    }
}

// ---------------- K4b: out_proj GEMM + skip -> g_xm ----------------
// grid (L/64, NSq), 256 threads, ~18KB smem
__global__ void __launch_bounds__(256)
k4b_outproj(const float* __restrict__ Wout, const float* __restrict__ skip) {
    __shared__ float ys[64*36];   // y tile [l][d-chunk 32]
    __shared__ float wsh[32*66];  // Wout^T chunk [dd][o]
    const int tid = threadIdx.x;
    const int s   = blockIdx.y;
    const int l0  = blockIdx.x * 64;

    const int og = tid & 31;   // o pair
    const int lg = tid >> 5;   // 8 l's each
    float acc0[8], acc1[8];
    #pragma unroll
    for (int j = 0; j < 8; j++) { acc0[j] = 0.f; acc1[j] = 0.f; }

    for (int dc = 0; dc < 4; dc++) {
        const int d0 = dc*32;
        __syncthreads();
        for (int i = tid; i < 32*64; i += 256) {
            int o = i >> 5, dd = i & 31;
            wsh[dd*66 + o] = Wout[o*128 + d0 + dd];
        }
        for (int i = tid; i < 64*32; i += 256) {
            int ll = i >> 5, dd = i & 31;
            ys[ll*36 + dd] = g_uraw[(s*LSEQ + l0 + ll)*128 + d0 + dd];
        }
        __syncthreads();
        #pragma unroll 4
        for (int dd = 0; dd < 32; dd++) {
            float2 wv = *(const float2*)&wsh[dd*66 + og*2];
            #pragma unroll
            for (int j = 0; j < 8; j++) {
                float yv = ys[(lg*8 + j)*36 + dd];
                acc0[j] += wv.x * yv;
                acc1[j] += wv.y * yv;
            }
        }
    }

    const float sk = skip[0];
    const int p = s >> 1, b = s & 1;
    const int o0 = og*2;
    #pragma unroll
    for (int j = 0; j < 8; j++) {
        int l = l0 + lg*8 + j;
        float2 pv = *(const float2*)&g_parts[(s*LSEQ + l)*64 + o0];
        float2 ov;
        ov.x = acc0[j] + sk*pv.x;
        ov.y = acc1[j] + sk*pv.y;
        *(float2*)&g_xm[(b*LSEQ + l)*256 + p*64 + o0] = ov;
    }
}

// ---------------- K5: final LN + 256x256 proj + bias + transpose ----------------
// grid (L/16, B, 2 o-halves), 256 threads, ~52KB -> 4 blocks/SM
__global__ void __launch_bounds__(256)
k5_ln_proj(const float* __restrict__ lng, const float* __restrict__ lnb,
           const float* __restrict__ Wp, const float* __restrict__ bp,
           float* __restrict__ out) {
    extern __shared__ float sm[];
    float* xs  = sm;             // 16 x 257
    float* wt  = xs + 16*257;    // 64 x 132 (c-chunk of Wp^T [c'][o_local]); reused as ysm 128x17
    float* gs  = wt + 64*132;    // 256
    float* bs  = gs + 256;       // 256
    float* mus = bs + 256;       // 16
    float* rss = mus + 16;       // 16

    const int tid = threadIdx.x;
    const int b   = blockIdx.y;
    const int z   = blockIdx.z;
    const int l0  = blockIdx.x * 16;

    gs[tid] = lng[tid]; bs[tid] = lnb[tid];
    #pragma unroll 4
    for (int i = 0; i < 16; i++)
        xs[i*257 + tid] = g_xm[(b*LSEQ + l0 + i)*256 + tid];
    __syncthreads();

    const int w = tid >> 5, lane = tid & 31;
    for (int i = 0; i < 2; i++) {
        int ll = w*2 + i;
        float s = 0.f, s2 = 0.f;
        #pragma unroll
        for (int j = 0; j < 8; j++) {
            float v = xs[ll*257 + lane + j*32];
            s += v; s2 += v*v;
        }
        #pragma unroll
        for (int o = 16; o > 0; o >>= 1) {
            s  += __shfl_xor_sync(0xffffffffu, s,  o);
            s2 += __shfl_xor_sync(0xffffffffu, s2, o);
        }
        if (lane == 0) {
            float mu = s * (1.f/256.f);
            mus[ll] = mu;
            rss[ll] = rsqrtf(s2 * (1.f/256.f) - mu*mu + 1e-5f);
        }
    }
    __syncthreads();
    #pragma unroll
    for (int ll = 0; ll < 16; ll++) {
        int cc = tid;
        xs[ll*257 + cc] = (xs[ll*257 + cc] - mus[ll]) * rss[ll] * gs[cc] + bs[cc];
    }

    // GEMM: thread = (to 32, tl 8): o_local = to*4, l = tl*2 + j
    const int to = tid >> 3, tl = tid & 7;
    const int o0 = to*4;
    float4 pb = *(const float4*)&bp[z*128 + o0];
    float a0[2], a1[2], a2[2], a3[2];
    #pragma unroll
    for (int j = 0; j < 2; j++) { a0[j]=pb.x; a1[j]=pb.y; a2[j]=pb.z; a3[j]=pb.w; }

    for (int c0 = 0; c0 < 256; c0 += 64) {
        __syncthreads();
        #pragma unroll 4
        for (int i = 0; i < 32; i++) {        // Wp chunk -> wt[c'][o_local]
            int idx = i*256 + tid;
            int ol = idx >> 6, cc = idx & 63;
            wt[cc*132 + ol] = Wp[(z*128 + ol)*256 + c0 + cc];
        }
        __syncthreads();
        #pragma unroll 4
        for (int cc = 0; cc < 64; cc++) {
            float4 wv = *(const float4*)&wt[cc*132 + o0];
            #pragma unroll
            for (int j = 0; j < 2; j++) {
                float xv = xs[(tl*2 + j)*257 + c0 + cc];
                a0[j] += wv.x * xv;
                a1[j] += wv.y * xv;
                a2[j] += wv.z * xv;
                a3[j] += wv.w * xv;
            }
        }
    }
    __syncthreads();

    float* ysm = wt;   // 128 x 17 overlay
    #pragma unroll
    for (int j = 0; j < 2; j++) {
        int l = tl*2 + j;
        ysm[(o0+0)*17 + l] = a0[j];
        ysm[(o0+1)*17 + l] = a1[j];
        ysm[(o0+2)*17 + l] = a2[j];
        ysm[(o0+3)*17 + l] = a3[j];
    }
    __syncthreads();
    #pragma unroll 4
    for (int i = tid; i < 128*16; i += 256) {
        int o = i >> 4, l = i & 15;
        out[(b*256 + z*128 + o)*LSEQ + l0 + l] = ysm[o*17 + l];
    }
}

// ---------------- launch ----------------
extern "C" void kernel_launch(void* const* d_in, const int* in_sizes, int n_in,
                              void* d_out, int out_size) {
    const float* x     = (const float*)d_in[0];
    const float* ln_g  = (const float*)d_in[1];
    const float* ln_b  = (const float*)d_in[2];
    const float* skip  = (const float*)d_in[3];
    const float* inw   = (const float*)d_in[4];
    const float* convw = (const float*)d_in[5];
    const float* convb = (const float*)d_in[6];
    const float* xprojw= (const float*)d_in[7];
    const float* dtw   = (const float*)d_in[8];
    const float* dtb   = (const float*)d_in[9];
    const float* A_log = (const float*)d_in[10];
    const float* Dp    = (const float*)d_in[11];
    const float* outw  = (const float*)d_in[12];
    const float* projw = (const float*)d_in[13];
    const float* projb = (const float*)d_in[14];
    float* out = (float*)d_out;

    const int SM1 = (16*257 + 64*132 + 256+256+16+16) * 4;
    const int SM2 = (19*130 + 16*130 + 36*130 + 16*40 + 128*5 + 128*5 + 128 + 128) * 4;
    const int SM5 = SM1;

    cudaFuncSetAttribute(k1_ln_inproj, cudaFuncAttributeMaxDynamicSharedMemorySize, SM1);
    cudaFuncSetAttribute(k2_conv,      cudaFuncAttributeMaxDynamicSharedMemorySize, SM2);
    cudaFuncSetAttribute(k5_ln_proj,   cudaFuncAttributeMaxDynamicSharedMemorySize, SM5);

    k0_check<<<1, 256>>>(A_log);
    k1_ln_inproj<<<dim3(LSEQ/16, 2, 2), 256, SM1>>>(x, ln_g, ln_b, inw);
    k2_conv<<<dim3(LSEQ/16, NSq), 256, SM2>>>(convw, convb, xprojw, dtw, dtb);
    k3_scan1<<<dim3(NCHK, NSq), 256>>>(A_log);
    k3b_carry<<<NCHAN/256, 256>>>();
    k4_scan2<<<dim3(NCHK, NSq), 256>>>(A_log, Dp);
    k4b_outproj<<<dim3(LSEQ/64, NSq), 256>>>(outw, skip);
    k5_ln_proj<<<dim3(LSEQ/16, 2, 2), 256, SM5>>>(ln_g, ln_b, projw, projb, out);
}